// round 1
// baseline (speedup 1.0000x reference)
#include <cuda_runtime.h>
#include <math.h>

#define N_ENT 100000
#define N_REL 64
#define EDIM  64
#define KN    32
#define BSZ   1024
#define SLOPE 0.2f

// Scratch (device globals; no allocation allowed)
__device__ __align__(16) float g_En[N_ENT * EDIM];   // normalized entity table, 25.6 MB (L2-resident)
__device__ __align__(16) float g_RwT[EDIM * N_REL];  // [f][r] = sum_e Rn[r][e] * att_w1[f][64+e]

// ---------------------------------------------------------------------------
// Kernel A: normalize E rows (lookup semantics: scale by 1/(n+1e-7) iff n>1)
// one warp per row, float2 per lane
// ---------------------------------------------------------------------------
__global__ void normalize_E_kernel(const float* __restrict__ E) {
    int row  = (blockIdx.x * blockDim.x + threadIdx.x) >> 5;
    int lane = threadIdx.x & 31;
    if (row >= N_ENT) return;
    float2 v = reinterpret_cast<const float2*>(E)[row * 32 + lane];
    float ss = v.x * v.x + v.y * v.y;
    #pragma unroll
    for (int o = 16; o > 0; o >>= 1) ss += __shfl_xor_sync(0xffffffffu, ss, o);
    float n  = sqrtf(ss);
    float sc = (n > 1.0f) ? (1.0f / (n + 1e-7f)) : 1.0f;
    float2 o2; o2.x = v.x * sc; o2.y = v.y * sc;
    reinterpret_cast<float2*>(g_En)[row * 32 + lane] = o2;
}

// ---------------------------------------------------------------------------
// Kernel B: Rn = normalize(R);  g_RwT[f*64+r] = sum_e Rn[r][e]*att_w1[f*128+64+e]
// single block, trivially cheap
// ---------------------------------------------------------------------------
__global__ void prep_Rw_kernel(const float* __restrict__ R,
                               const float* __restrict__ att_w1) {
    __shared__ float sRn[N_REL * EDIM];
    __shared__ float sScale[N_REL];
    int tid = threadIdx.x;  // 256
    for (int i = tid; i < N_REL * EDIM; i += 256) sRn[i] = R[i];
    __syncthreads();
    if (tid < N_REL) {
        float ss = 0.f;
        for (int e = 0; e < EDIM; e++) { float v = sRn[tid * EDIM + e]; ss += v * v; }
        float n = sqrtf(ss);
        sScale[tid] = (n > 1.0f) ? (1.0f / (n + 1e-7f)) : 1.0f;
    }
    __syncthreads();
    for (int i = tid; i < N_REL * EDIM; i += 256) sRn[i] *= sScale[i >> 6];
    __syncthreads();
    for (int i = tid; i < EDIM * N_REL; i += 256) {
        int f = i >> 6, r = i & 63;
        const float* w = att_w1 + f * 128 + 64;
        float acc = 0.f;
        for (int e = 0; e < EDIM; e++) acc += sRn[r * EDIM + e] * w[e];
        g_RwT[i] = acc;  // [f][r]
    }
}

// ---------------------------------------------------------------------------
// Main kernel: one block per batch element, 256 threads
// ---------------------------------------------------------------------------
__global__ __launch_bounds__(256) void kgan_main_kernel(
    const int*   __restrict__ entity_idx,
    const int*   __restrict__ adj_entity,
    const int*   __restrict__ adj_relation,
    const float* __restrict__ att_w1,
    const float* __restrict__ att_w2,
    const float* __restrict__ att_w3,
    const float* __restrict__ wx_w,
    const float* __restrict__ wx_b,
    const float* __restrict__ wc_w,
    const float* __restrict__ wc_b,
    float*       __restrict__ out)
{
    __shared__ __align__(16) float sRwT[64 * 64];  // [f][r]
    __shared__ __align__(16) float sW2 [64 * 64];  // att_w2 row-major [g][f]
    __shared__ float sw3[64];
    __shared__ float sh[64], shsum[64], sbh1[64], sbh2[64];
    __shared__ float st1[32 * 64];                 // t1 rows [k][f]
    __shared__ int   sEnt1[32], sRel1[32];
    __shared__ float sPa[2 * 128];                 // stage-7 partial dot (two g-halves)
    __shared__ float sE1[64], sE2[64];             // exp(sigmoid(a)) per relation
    __shared__ __align__(16) float2 sAggP2[8 * 32];// per-warp hop2 partial agg
    __shared__ float sSP[8];
    __shared__ float sAgg[64], sV[64];
    __shared__ float sWk[32];

    const int tid  = threadIdx.x;
    const int b    = blockIdx.x;
    const int lane = tid & 31;
    const int warp = tid >> 5;

    // ---- load weight tables into shared ----
    for (int i = tid; i < 4096; i += 256) sRwT[i] = g_RwT[i];
    for (int i = tid; i < 4096; i += 256) sW2[i]  = att_w2[i];
    if (tid < 64) sw3[tid] = att_w3[tid];

    const int eidx = entity_idx[b];
    if (tid < 32) {
        sEnt1[tid] = adj_entity[eidx * KN + tid];
        sRel1[tid] = adj_relation[eidx * KN + tid];
    }
    if (tid < 64) sh[tid] = g_En[eidx * 64 + tid];
    __syncthreads();

    // ---- t1 = En[ent1] (32x64) ----
    for (int i = tid; i < 2048; i += 256) {
        int k = i >> 6, f = i & 63;
        st1[i] = g_En[sEnt1[k] * 64 + f];
    }
    __syncthreads();

    // ---- hsum = t1.sum(axis=0) ----
    if (tid < 64) {
        float s = 0.f;
        #pragma unroll
        for (int k = 0; k < 32; k++) s += st1[k * 64 + tid];
        shsum[tid] = s;
    }
    __syncthreads();

    // ---- bh1 = h @ w1h^T, bh2 = hsum @ w1h^T ----
    if (tid < 128) {
        int f = tid & 63;
        const float*  src = (tid < 64) ? sh : shsum;
        const float4* w   = reinterpret_cast<const float4*>(att_w1 + f * 128);
        float acc = 0.f;
        #pragma unroll
        for (int e4 = 0; e4 < 16; e4++) {
            float4 wv = w[e4];
            acc += wv.x * src[e4 * 4] + wv.y * src[e4 * 4 + 1]
                 + wv.z * src[e4 * 4 + 2] + wv.w * src[e4 * 4 + 3];
        }
        if (tid < 64) sbh1[f] = acc; else sbh2[f] = acc;
    }
    __syncthreads();

    // ---- stage 7: per-relation attention logits (128 tasks x 2 g-halves) ----
    {
        const int task  = tid & 127;          // [0,64): hop1 rel r; [64,128): hop2 rel r
        const int ghalf = tid >> 7;
        const int r     = task & 63;
        const float* bh = (task < 64) ? sbh1 : sbh2;

        float hid[64];
        #pragma unroll
        for (int f = 0; f < 64; f++)
            hid[f] = fmaxf(bh[f] + sRwT[f * 64 + r], 0.0f);

        const float4* w2v = reinterpret_cast<const float4*>(sW2);
        float a = 0.0f;
        const int g0 = ghalf * 32;
        #pragma unroll 2
        for (int g = g0; g < g0 + 32; g++) {
            float acc0 = 0.f, acc1 = 0.f;
            #pragma unroll
            for (int f4 = 0; f4 < 16; f4 += 2) {
                float4 wa = w2v[g * 16 + f4];
                float4 wb = w2v[g * 16 + f4 + 1];
                acc0 += wa.x * hid[f4 * 4]     + wa.y * hid[f4 * 4 + 1]
                      + wa.z * hid[f4 * 4 + 2] + wa.w * hid[f4 * 4 + 3];
                acc1 += wb.x * hid[f4 * 4 + 4] + wb.y * hid[f4 * 4 + 5]
                      + wb.z * hid[f4 * 4 + 6] + wb.w * hid[f4 * 4 + 7];
            }
            a += sw3[g] * fmaxf(acc0 + acc1, 0.0f);
        }
        sPa[ghalf * 128 + task] = a;
    }
    __syncthreads();

    if (tid < 128) {
        float av  = sPa[tid] + sPa[128 + tid];
        float sig = 1.0f / (1.0f + expf(-av));
        float e   = expf(sig);                 // logits in (0,1): no max-sub needed
        if (tid < 64) sE1[tid] = e; else sE2[tid - 64] = e;
    }
    __syncthreads();

    // ---- hop 1: softmax-weighted aggregation over 32 neighbors ----
    if (tid < 32) sWk[tid] = sE1[sRel1[tid]];
    __syncthreads();
    if (tid < 64) {
        float s = 0.f, acc = 0.f;
        #pragma unroll
        for (int k = 0; k < 32; k++) { float w = sWk[k]; s += w; acc += w * st1[k * 64 + tid]; }
        sAgg[tid] = acc / s;
    }
    __syncthreads();
    // v1 = leaky(agg @ wx_w^T + wx_b)
    if (tid < 64) {
        const float4* w = reinterpret_cast<const float4*>(wx_w + tid * 64);
        float acc = wx_b[tid];
        #pragma unroll
        for (int e4 = 0; e4 < 16; e4++) {
            float4 wv = w[e4];
            acc += wv.x * sAgg[e4 * 4]     + wv.y * sAgg[e4 * 4 + 1]
                 + wv.z * sAgg[e4 * 4 + 2] + wv.w * sAgg[e4 * 4 + 3];
        }
        sV[tid] = (acc >= 0.f) ? acc : SLOPE * acc;
    }
    __syncthreads();
    // emb1 = leaky([h, v1] @ wc_w^T + wc_b); also emit h
    if (tid < 64) {
        const float4* w = reinterpret_cast<const float4*>(wc_w + tid * 128);
        float acc = wc_b[tid];
        #pragma unroll
        for (int e4 = 0; e4 < 16; e4++) {
            float4 wv = w[e4];
            acc += wv.x * sh[e4 * 4]     + wv.y * sh[e4 * 4 + 1]
                 + wv.z * sh[e4 * 4 + 2] + wv.w * sh[e4 * 4 + 3];
        }
        #pragma unroll
        for (int e4 = 0; e4 < 16; e4++) {
            float4 wv = w[16 + e4];
            acc += wv.x * sV[e4 * 4]     + wv.y * sV[e4 * 4 + 1]
                 + wv.z * sV[e4 * 4 + 2] + wv.w * sV[e4 * 4 + 3];
        }
        out[b * 192 + 64 + tid]  = (acc >= 0.f) ? acc : SLOPE * acc;
        out[b * 192 + 128 + tid] = sh[tid];
    }

    // ---- hop 2: 1024 neighbors; warp handles n1 in [warp*4, warp*4+4) ----
    float accx = 0.f, accy = 0.f, ssum = 0.f;
    #pragma unroll 1
    for (int j = 0; j < 4; j++) {
        const int n1   = warp * 4 + j;
        const int base = sEnt1[n1] * KN;
        int   ei = adj_entity[base + lane];
        int   ri = adj_relation[base + lane];
        float wt = sE2[ri];
        ssum += wt;
        #pragma unroll 8
        for (int k = 0; k < 32; k++) {
            int   idx = __shfl_sync(0xffffffffu, ei, k);
            float wv  = __shfl_sync(0xffffffffu, wt, k);
            float2 v  = reinterpret_cast<const float2*>(g_En)[idx * 32 + lane];
            accx += wv * v.x;
            accy += wv * v.y;
        }
    }
    #pragma unroll
    for (int o = 16; o > 0; o >>= 1) ssum += __shfl_xor_sync(0xffffffffu, ssum, o);
    if (lane == 0) sSP[warp] = ssum;
    sAggP2[warp * 32 + lane] = make_float2(accx, accy);
    __syncthreads();

    if (tid < 64) {
        const float* aggp = reinterpret_cast<const float*>(sAggP2);
        float s2 = 0.f;
        #pragma unroll
        for (int w = 0; w < 8; w++) s2 += sSP[w];
        float acc = 0.f;
        #pragma unroll
        for (int w = 0; w < 8; w++) acc += aggp[w * 64 + tid];
        sAgg[tid] = acc / s2;
    }
    __syncthreads();
    // v2 = leaky(agg2 @ wx_w^T + wx_b)
    if (tid < 64) {
        const float4* w = reinterpret_cast<const float4*>(wx_w + tid * 64);
        float acc = wx_b[tid];
        #pragma unroll
        for (int e4 = 0; e4 < 16; e4++) {
            float4 wv = w[e4];
            acc += wv.x * sAgg[e4 * 4]     + wv.y * sAgg[e4 * 4 + 1]
                 + wv.z * sAgg[e4 * 4 + 2] + wv.w * sAgg[e4 * 4 + 3];
        }
        sV[tid] = (acc >= 0.f) ? acc : SLOPE * acc;
    }
    __syncthreads();
    // emb2 = leaky([hsum, v2] @ wc_w^T + wc_b)
    if (tid < 64) {
        const float4* w = reinterpret_cast<const float4*>(wc_w + tid * 128);
        float acc = wc_b[tid];
        #pragma unroll
        for (int e4 = 0; e4 < 16; e4++) {
            float4 wv = w[e4];
            acc += wv.x * shsum[e4 * 4]     + wv.y * shsum[e4 * 4 + 1]
                 + wv.z * shsum[e4 * 4 + 2] + wv.w * shsum[e4 * 4 + 3];
        }
        #pragma unroll
        for (int e4 = 0; e4 < 16; e4++) {
            float4 wv = w[16 + e4];
            acc += wv.x * sV[e4 * 4]     + wv.y * sV[e4 * 4 + 1]
                 + wv.z * sV[e4 * 4 + 2] + wv.w * sV[e4 * 4 + 3];
        }
        out[b * 192 + tid] = (acc >= 0.f) ? acc : SLOPE * acc;
    }
}

extern "C" void kernel_launch(void* const* d_in, const int* in_sizes, int n_in,
                              void* d_out, int out_size) {
    const int*   entity_idx   = (const int*)  d_in[0];
    const int*   adj_entity   = (const int*)  d_in[1];
    const int*   adj_relation = (const int*)  d_in[2];
    const float* E            = (const float*)d_in[3];
    const float* R            = (const float*)d_in[4];
    const float* att_w1       = (const float*)d_in[5];
    const float* att_w2       = (const float*)d_in[6];
    const float* att_w3       = (const float*)d_in[7];
    const float* wx_w         = (const float*)d_in[8];
    const float* wx_b         = (const float*)d_in[9];
    const float* wc_w         = (const float*)d_in[10];
    const float* wc_b         = (const float*)d_in[11];
    float* out = (float*)d_out;

    normalize_E_kernel<<<(N_ENT + 7) / 8, 256>>>(E);
    prep_Rw_kernel<<<1, 256>>>(R, att_w1);
    kgan_main_kernel<<<BSZ, 256>>>(entity_idx, adj_entity, adj_relation,
                                   att_w1, att_w2, att_w3,
                                   wx_w, wx_b, wc_w, wc_b, out);
}